// round 16
// baseline (speedup 1.0000x reference)
#include <cuda_runtime.h>
#include <cuda_bf16.h>
#include <math_constants.h>
#include <cstdint>

// Problem constants
#define BATCH 2
#define SEQ 2048
#define DIM 4096
#define NH 32
#define NKV 8
#define HD 128
#define TOKENS (BATCH * SEQ)   // 4096

// ---------------------------------------------------------------------------
// Scratch (device globals; no runtime allocation allowed)
// ---------------------------------------------------------------------------
__device__ __nv_bfloat16 g_data_hi[(size_t)TOKENS * DIM];
__device__ __nv_bfloat16 g_data_lo[(size_t)TOKENS * DIM];
__device__ __nv_bfloat16 g_wq_hi[(size_t)(NH * HD) * DIM];
__device__ __nv_bfloat16 g_wq_lo[(size_t)(NH * HD) * DIM];
__device__ __nv_bfloat16 g_wk_hi[(size_t)(NKV * HD) * DIM];
__device__ __nv_bfloat16 g_wk_lo[(size_t)(NKV * HD) * DIM];
__device__ __nv_bfloat16 g_wv_hi[(size_t)(NKV * HD) * DIM];
__device__ __nv_bfloat16 g_wv_lo[(size_t)(NKV * HD) * DIM];
__device__ __nv_bfloat16 g_wo_hi[(size_t)DIM * (NH * HD)];
__device__ __nv_bfloat16 g_wo_lo[(size_t)DIM * (NH * HD)];
__device__ __nv_bfloat16 g_attn_hi[(size_t)TOKENS * (NH * HD)];
__device__ __nv_bfloat16 g_attn_lo[(size_t)TOKENS * (NH * HD)];

// Post-RoPE split Q/K and split V (bf16 hi/lo) — written by gemm_qkv epilogue
__device__ __nv_bfloat16 g_qs_hi[(size_t)TOKENS * (NH * HD)];
__device__ __nv_bfloat16 g_qs_lo[(size_t)TOKENS * (NH * HD)];
__device__ __nv_bfloat16 g_ks_hi[(size_t)TOKENS * (NKV * HD)];
__device__ __nv_bfloat16 g_ks_lo[(size_t)TOKENS * (NKV * HD)];
__device__ __nv_bfloat16 g_vs_hi[(size_t)TOKENS * (NKV * HD)];
__device__ __nv_bfloat16 g_vs_lo[(size_t)TOKENS * (NKV * HD)];

// ---------------------------------------------------------------------------
// PTX helpers
// ---------------------------------------------------------------------------
__device__ __forceinline__ uint32_t smem_u32(const void* p) {
    uint32_t a;
    asm("{ .reg .u64 t; cvta.to.shared.u64 t, %1; cvt.u32.u64 %0, t; }"
        : "=r"(a) : "l"(p));
    return a;
}
__device__ __forceinline__ void cp16(uint32_t saddr, const void* g) {
    asm volatile("cp.async.cg.shared.global [%0], [%1], 16;" :: "r"(saddr), "l"(g));
}
__device__ __forceinline__ void ldm_x4(uint32_t* r, uint32_t addr) {
    asm volatile("ldmatrix.sync.aligned.m8n8.x4.shared.b16 {%0,%1,%2,%3}, [%4];"
                 : "=r"(r[0]), "=r"(r[1]), "=r"(r[2]), "=r"(r[3]) : "r"(addr));
}
__device__ __forceinline__ void ldm_x4t(uint32_t* r, uint32_t addr) {
    asm volatile("ldmatrix.sync.aligned.m8n8.x4.trans.shared.b16 {%0,%1,%2,%3}, [%4];"
                 : "=r"(r[0]), "=r"(r[1]), "=r"(r[2]), "=r"(r[3]) : "r"(addr));
}
__device__ __forceinline__ void mma16816(float* d, const uint32_t* a,
                                         uint32_t b0, uint32_t b1) {
    asm volatile(
        "mma.sync.aligned.m16n8k16.row.col.f32.bf16.bf16.f32 "
        "{%0,%1,%2,%3}, {%4,%5,%6,%7}, {%8,%9}, {%0,%1,%2,%3};"
        : "+f"(d[0]), "+f"(d[1]), "+f"(d[2]), "+f"(d[3])
        : "r"(a[0]), "r"(a[1]), "r"(a[2]), "r"(a[3]), "r"(b0), "r"(b1));
}
__device__ __forceinline__ float ex2(float x) {
    float r;
    asm("ex2.approx.f32 %0, %1;" : "=f"(r) : "f"(x));
    return r;
}
__device__ __forceinline__ void split2(float a, float b, uint32_t& hi, uint32_t& lo) {
    __nv_bfloat16 ha = __float2bfloat16(a), hb = __float2bfloat16(b);
    __nv_bfloat162 H(ha, hb);
    __nv_bfloat162 L(__float2bfloat16(a - __bfloat162float(ha)),
                     __float2bfloat16(b - __bfloat162float(hb)));
    hi = *reinterpret_cast<uint32_t*>(&H);
    lo = *reinterpret_cast<uint32_t*>(&L);
}
__device__ __forceinline__ void tsplit2(float a, float b, uint32_t& hi, uint32_t& lo) {
    uint32_t ua = __float_as_uint(a), ub = __float_as_uint(b);
    asm("prmt.b32 %0, %1, %2, 0x7632;" : "=r"(hi) : "r"(ua), "r"(ub));
    float ra = a - __uint_as_float(ua & 0xFFFF0000u);
    float rb = b - __uint_as_float(ub & 0xFFFF0000u);
    asm("cvt.rn.bf16x2.f32 %0, %1, %2;" : "=r"(lo) : "f"(rb), "f"(ra));
}

// ---------------------------------------------------------------------------
// HMMA GEMM, tile 256x128, BK=32, 3-stage cp.async (60KB/stage), 8 warps 4m x 2n.
// 3 split terms per chunk. One barrier per chunk; prefetch distance 2.
// EPI: 0 = fp32 C, 1 = rope+scale+split -> Ohi/Olo, 2 = split-only -> Ohi/Olo
// ---------------------------------------------------------------------------
#define GK 4096
#define BKC 32
#define NCH (GK / BKC)               // 128
#define LDA 40
#define A_ARR (256 * LDA * 2)        // 20480
#define B_ARR (128 * LDA * 2)        // 10240
#define OFF_ALO A_ARR
#define OFF_BHI (2 * A_ARR)
#define OFF_BLO (2 * A_ARR + B_ARR)
#define STG_B (2 * A_ARR + 2 * B_ARR)   // 61440
#define GSTAGES 3
#define GEMM_SMEM (GSTAGES * STG_B)     // 184320

__device__ __forceinline__ void load_chunk_g(
    int kc, uint32_t sb, int tid, int m0, int n0,
    const __nv_bfloat16* __restrict__ Ahi, const __nv_bfloat16* __restrict__ Alo,
    const __nv_bfloat16* __restrict__ Bhi, const __nv_bfloat16* __restrict__ Blo)
{
    const size_t ke = (size_t)kc * BKC;
    const int r0 = tid >> 2;             // 0..63
    const int seg = (tid & 3) * 8;       // elem offset in 32-elem row
#pragma unroll
    for (int it = 0; it < 4; it++) {     // A: 256 rows
        int r = r0 + it * 64;
        uint32_t srow = sb + (uint32_t)(r * LDA + seg) * 2;
        size_t ga = (size_t)(m0 + r) * GK + ke + seg;
        cp16(srow,           Ahi + ga);
        cp16(srow + OFF_ALO, Alo + ga);
    }
#pragma unroll
    for (int it = 0; it < 2; it++) {     // B: 128 rows
        int r = r0 + it * 64;
        uint32_t srow = sb + OFF_BHI + (uint32_t)(r * LDA + seg) * 2;
        size_t gb = (size_t)(n0 + r) * GK + ke + seg;
        cp16(srow,                     Bhi + gb);
        cp16(srow + (OFF_BLO - OFF_BHI), Blo + gb);
    }
    asm volatile("cp.async.commit_group;" ::: "memory");
}

template <int EPI>
__device__ __forceinline__ void gemm_core(
    const __nv_bfloat16* __restrict__ Ahi, const __nv_bfloat16* __restrict__ Alo,
    const __nv_bfloat16* __restrict__ Bhi, const __nv_bfloat16* __restrict__ Blo,
    float* __restrict__ C,
    __nv_bfloat16* __restrict__ Ohi, __nv_bfloat16* __restrict__ Olo,
    const float* __restrict__ cosT, const float* __restrict__ sinT, float scale,
    int Ng, int m0, int n0, char* dsm)
{
    const uint32_t base = smem_u32(dsm);
    const int tid = threadIdx.x;
    const int lane = tid & 31;
    const int w = tid >> 5;
    const int wm = (w >> 1) * 64;   // 4 m-warps of 64 rows
    const int wn = (w & 1) * 64;    // 2 n-warps of 64 cols

    float acc[4][8][4];
#pragma unroll
    for (int mf = 0; mf < 4; mf++)
#pragma unroll
        for (int j = 0; j < 8; j++)
#pragma unroll
            for (int q = 0; q < 4; q++) acc[mf][j][q] = 0.f;

    const uint32_t a_off = (uint32_t)(((lane & 15)) * LDA + ((lane >> 4) * 8)) * 2;
    const uint32_t b_off = (uint32_t)(((lane & 7) + ((lane >> 4) << 3)) * LDA
                                      + (((lane >> 3) & 1) * 8)) * 2;

    load_chunk_g(0, base, tid, m0, n0, Ahi, Alo, Bhi, Blo);
    load_chunk_g(1, base + STG_B, tid, m0, n0, Ahi, Alo, Bhi, Blo);

    int st = 0;
    for (int c = 0; c < NCH; c++) {
        // load(c) was committed 2 groups ago -> wait until <=1 pending
        asm volatile("cp.async.wait_group 1;" ::: "memory");
        __syncthreads();   // all warps past MMAs(c-1); load(c) visible

        int st2 = st + 2; if (st2 >= GSTAGES) st2 -= GSTAGES;
        if (c + 2 < NCH)
            load_chunk_g(c + 2, base + st2 * STG_B, tid, m0, n0, Ahi, Alo, Bhi, Blo);
        else
            asm volatile("cp.async.commit_group;" ::: "memory");

        const uint32_t sb = base + st * STG_B;
        const uint32_t ab = sb + (uint32_t)(wm * LDA * 2) + a_off;
        const uint32_t bb = sb + OFF_BHI + (uint32_t)(wn * LDA * 2) + b_off;

#pragma unroll
        for (int ks = 0; ks < 2; ks++) {
            uint32_t ah[4][4], al[4][4];
#pragma unroll
            for (int mf = 0; mf < 4; mf++) {
                ldm_x4(ah[mf], ab + mf * (16 * LDA * 2) + ks * 32);
                ldm_x4(al[mf], ab + OFF_ALO + mf * (16 * LDA * 2) + ks * 32);
            }
#pragma unroll
            for (int g = 0; g < 4; g++) {
                uint32_t bh[4];
                ldm_x4(bh, bb + g * (16 * LDA * 2) + ks * 32);
#pragma unroll
                for (int mf = 0; mf < 4; mf++) {
                    mma16816(acc[mf][2 * g],     ah[mf], bh[0], bh[1]);
                    mma16816(acc[mf][2 * g + 1], ah[mf], bh[2], bh[3]);
                }
#pragma unroll
                for (int mf = 0; mf < 4; mf++) {
                    mma16816(acc[mf][2 * g],     al[mf], bh[0], bh[1]);
                    mma16816(acc[mf][2 * g + 1], al[mf], bh[2], bh[3]);
                }
                uint32_t bl[4];
                ldm_x4(bl, bb + (OFF_BLO - OFF_BHI) + g * (16 * LDA * 2) + ks * 32);
#pragma unroll
                for (int mf = 0; mf < 4; mf++) {
                    mma16816(acc[mf][2 * g],     ah[mf], bl[0], bl[1]);
                    mma16816(acc[mf][2 * g + 1], ah[mf], bl[2], bl[3]);
                }
            }
        }
        st = st + 1; if (st >= GSTAGES) st -= GSTAGES;
    }

    const int gr = lane >> 2;
    const int gc = (lane & 3) * 2;

    if (EPI == 0) {
#pragma unroll
        for (int mf = 0; mf < 4; mf++) {
            const int row = m0 + wm + mf * 16 + gr;
#pragma unroll
            for (int j = 0; j < 8; j++) {
                const int col = n0 + wn + j * 8 + gc;
                *(float2*)&C[(size_t)row * Ng + col] =
                    make_float2(acc[mf][j][0], acc[mf][j][1]);
                *(float2*)&C[(size_t)(row + 8) * Ng + col] =
                    make_float2(acc[mf][j][2], acc[mf][j][3]);
            }
        }
    } else if (EPI == 2) {
#pragma unroll
        for (int mf = 0; mf < 4; mf++) {
            const int row = m0 + wm + mf * 16 + gr;
#pragma unroll
            for (int j = 0; j < 8; j++) {
                const int col = n0 + wn + j * 8 + gc;
                uint32_t h, l;
                split2(acc[mf][j][0], acc[mf][j][1], h, l);
                *(uint32_t*)&Ohi[(size_t)row * Ng + col] = h;
                *(uint32_t*)&Olo[(size_t)row * Ng + col] = l;
                split2(acc[mf][j][2], acc[mf][j][3], h, l);
                *(uint32_t*)&Ohi[(size_t)(row + 8) * Ng + col] = h;
                *(uint32_t*)&Olo[(size_t)(row + 8) * Ng + col] = l;
            }
        }
    } else {
        // RoPE epilogue: tile cols = one head (128). Odd n-warps (d in [64,128))
        // stash to smem; even n-warps combine (d, d+64) pairs.
        __syncthreads();
        float* xs = (float*)dsm;   // [256][66] = 67584 B
        if (w & 1) {
#pragma unroll
            for (int mf = 0; mf < 4; mf++) {
                const int rl = wm + mf * 16 + gr;
#pragma unroll
                for (int j = 0; j < 8; j++) {
                    const int dd = j * 8 + gc;
                    xs[rl * 66 + dd]           = acc[mf][j][0];
                    xs[rl * 66 + dd + 1]       = acc[mf][j][1];
                    xs[(rl + 8) * 66 + dd]     = acc[mf][j][2];
                    xs[(rl + 8) * 66 + dd + 1] = acc[mf][j][3];
                }
            }
        }
        __syncthreads();
        if (!(w & 1)) {
#pragma unroll
            for (int mf = 0; mf < 4; mf++) {
#pragma unroll
                for (int fr = 0; fr < 2; fr++) {
                    const int rl = wm + mf * 16 + gr + fr * 8;
                    const int row = m0 + rl;
                    const int s = row & (SEQ - 1);
#pragma unroll
                    for (int j = 0; j < 8; j++) {
                        const int d = j * 8 + gc;
                        float x1a = acc[mf][j][fr * 2];
                        float x1b = acc[mf][j][fr * 2 + 1];
                        float x2a = xs[rl * 66 + d];
                        float x2b = xs[rl * 66 + d + 1];
                        float c0 = cosT[s * HD + d],     s0 = sinT[s * HD + d];
                        float c1 = cosT[s * HD + d + 1], s1 = sinT[s * HD + d + 1];
                        float y1a = (x1a * c0 - x2a * s0) * scale;
                        float y2a = (x2a * c0 + x1a * s0) * scale;
                        float y1b = (x1b * c1 - x2b * s1) * scale;
                        float y2b = (x2b * c1 + x1b * s1) * scale;
                        uint32_t h, l;
                        split2(y1a, y1b, h, l);
                        *(uint32_t*)&Ohi[(size_t)row * Ng + n0 + d] = h;
                        *(uint32_t*)&Olo[(size_t)row * Ng + n0 + d] = l;
                        split2(y2a, y2b, h, l);
                        *(uint32_t*)&Ohi[(size_t)row * Ng + n0 + 64 + d] = h;
                        *(uint32_t*)&Olo[(size_t)row * Ng + n0 + 64 + d] = l;
                    }
                }
            }
        }
    }
}

#define QSCALE (0.08838834764831845f * 1.4426950408889634f)

// Fused QKV projection + RoPE + split: bx 0..31 Q, 32..39 K, 40..47 V; by = 256-row tile
__global__ __launch_bounds__(256, 1) void gemm_qkv(
    const __nv_bfloat16* __restrict__ dh, const __nv_bfloat16* __restrict__ dl,
    const __nv_bfloat16* __restrict__ wqh, const __nv_bfloat16* __restrict__ wql,
    const __nv_bfloat16* __restrict__ wkh, const __nv_bfloat16* __restrict__ wkl,
    const __nv_bfloat16* __restrict__ wvh, const __nv_bfloat16* __restrict__ wvl,
    __nv_bfloat16* __restrict__ qsh, __nv_bfloat16* __restrict__ qsl,
    __nv_bfloat16* __restrict__ ksh, __nv_bfloat16* __restrict__ ksl,
    __nv_bfloat16* __restrict__ vsh, __nv_bfloat16* __restrict__ vsl,
    const float* __restrict__ cosT, const float* __restrict__ sinT)
{
    extern __shared__ char dsm[];
    const int bx = blockIdx.x;
    const int m0 = blockIdx.y * 256;
    if (bx < 32) {
        gemm_core<1>(dh, dl, wqh, wql, nullptr, qsh, qsl, cosT, sinT, QSCALE,
                     NH * HD, m0, bx * 128, dsm);
    } else if (bx < 40) {
        gemm_core<1>(dh, dl, wkh, wkl, nullptr, ksh, ksl, cosT, sinT, 1.0f,
                     NKV * HD, m0, (bx - 32) * 128, dsm);
    } else {
        gemm_core<2>(dh, dl, wvh, wvl, nullptr, vsh, vsl, nullptr, nullptr, 1.0f,
                     NKV * HD, m0, (bx - 40) * 128, dsm);
    }
}

// O projection
__global__ __launch_bounds__(256, 1) void gemm_mm(
    const __nv_bfloat16* __restrict__ Ahi, const __nv_bfloat16* __restrict__ Alo,
    const __nv_bfloat16* __restrict__ Bhi, const __nv_bfloat16* __restrict__ Blo,
    float* __restrict__ C, int Ng)
{
    extern __shared__ char dsm[];
    gemm_core<0>(Ahi, Alo, Bhi, Blo, C, nullptr, nullptr, nullptr, nullptr, 1.0f,
                 Ng, blockIdx.y * 256, blockIdx.x * 128, dsm);
}

// ---------------------------------------------------------------------------
// Splits: two launches (weights; data) so flash lands at launch #4 for ncu
// ---------------------------------------------------------------------------
#define SPLIT_N_WQ    4194304
#define SPLIT_N_WK    1048576
#define SPLIT_N_WV    1048576
#define SPLIT_N_WO    4194304
#define SPLIT_W_TOTAL (SPLIT_N_WQ + SPLIT_N_WK + SPLIT_N_WV + SPLIT_N_WO)
#define SPLIT_N_DATA  4194304

__global__ void split_w(
    const float* __restrict__ Wq, const float* __restrict__ Wk,
    const float* __restrict__ Wv, const float* __restrict__ Wo,
    __nv_bfloat16* __restrict__ qh, __nv_bfloat16* __restrict__ ql,
    __nv_bfloat16* __restrict__ kh, __nv_bfloat16* __restrict__ kl,
    __nv_bfloat16* __restrict__ vh, __nv_bfloat16* __restrict__ vl,
    __nv_bfloat16* __restrict__ oh, __nv_bfloat16* __restrict__ ol)
{
    int i = blockIdx.x * 256 + threadIdx.x;
    if (i >= SPLIT_W_TOTAL) return;
    const float* src; __nv_bfloat16 *hi, *lo; int off;
    if (i < SPLIT_N_WQ) { src = Wq; hi = qh; lo = ql; off = 0; }
    else if (i < SPLIT_N_WQ + SPLIT_N_WK)
        { src = Wk; hi = kh; lo = kl; off = SPLIT_N_WQ; }
    else if (i < SPLIT_N_WQ + SPLIT_N_WK + SPLIT_N_WV)
        { src = Wv; hi = vh; lo = vl; off = SPLIT_N_WQ + SPLIT_N_WK; }
    else
        { src = Wo; hi = oh; lo = ol; off = SPLIT_N_WQ + SPLIT_N_WK + SPLIT_N_WV; }
    int j = i - off;
    float4 val = ((const float4*)src)[j];
    uint32_t h01, l01, h23, l23;
    split2(val.x, val.y, h01, l01);
    split2(val.z, val.w, h23, l23);
    ((uint32_t*)hi)[j * 2]     = h01;
    ((uint32_t*)hi)[j * 2 + 1] = h23;
    ((uint32_t*)lo)[j * 2]     = l01;
    ((uint32_t*)lo)[j * 2 + 1] = l23;
}

__global__ void split_d(const float* __restrict__ x,
                        __nv_bfloat16* __restrict__ hi,
                        __nv_bfloat16* __restrict__ lo)
{
    int i = blockIdx.x * 256 + threadIdx.x;
    if (i >= SPLIT_N_DATA) return;
    float4 v = ((const float4*)x)[i];
    uint32_t h01, l01, h23, l23;
    split2(v.x, v.y, h01, l01);
    split2(v.z, v.w, h23, l23);
    ((uint32_t*)hi)[i * 2]     = h01;
    ((uint32_t*)hi)[i * 2 + 1] = h23;
    ((uint32_t*)lo)[i * 2]     = l01;
    ((uint32_t*)lo)[i * 2 + 1] = l23;
}

// ---------------------------------------------------------------------------
// Flash attention on HMMA (round-10 best version, unchanged).
// BQ=128, BKV=64, 8 warps x 16 q-rows, 2-stage KV double buffer.
// ---------------------------------------------------------------------------
#define LDV 136
#define LDVB (LDV * 2)
#define FBUF (64 * LDVB)
#define FSTG (4 * FBUF)
#define FLASH2_SMEM (2 * FSTG)

__device__ __forceinline__ void load_kv(uint32_t sb, int tid,
    const __nv_bfloat16* __restrict__ khi, const __nv_bfloat16* __restrict__ klo,
    const __nv_bfloat16* __restrict__ vhi, const __nv_bfloat16* __restrict__ vlo,
    size_t kvbase)
{
#pragma unroll
    for (int i = 0; i < 4; i++) {
        int idx = tid + i * 256;
        int r = idx >> 4, sg = idx & 15;
        size_t g = kvbase + (size_t)r * (NKV * HD) + sg * 8;
        uint32_t s = sb + r * LDVB + sg * 16;
        cp16(s,            khi + g);
        cp16(s + FBUF,     klo + g);
        cp16(s + 2 * FBUF, vhi + g);
        cp16(s + 3 * FBUF, vlo + g);
    }
    asm volatile("cp.async.commit_group;" ::: "memory");
}

__global__ __launch_bounds__(256) void flash_mma(
    const __nv_bfloat16* __restrict__ qhi, const __nv_bfloat16* __restrict__ qlo,
    const __nv_bfloat16* __restrict__ khi, const __nv_bfloat16* __restrict__ klo,
    const __nv_bfloat16* __restrict__ vhi, const __nv_bfloat16* __restrict__ vlo,
    __nv_bfloat16* __restrict__ ohi, __nv_bfloat16* __restrict__ olo)
{
    extern __shared__ char dsm[];
    const uint32_t base = smem_u32(dsm);
    const int tid = threadIdx.x;
    const int lane = tid & 31;
    const int w = tid >> 5;
    const int qb = gridDim.x - 1 - blockIdx.x;   // heavy tiles first
    const int bh = blockIdx.y;
    const int b = bh / NH, h = bh % NH;
    const int kh = h / (NH / NKV);
    const int q0 = qb * 128;

    const size_t qbase = ((size_t)b * SEQ + q0) * (NH * HD) + (size_t)h * HD;
    const size_t kvh   = ((size_t)b * SEQ) * (NKV * HD) + (size_t)kh * HD;

#pragma unroll
    for (int i = 0; i < 8; i++) {
        int idx = tid + i * 256;
        int r = idx >> 4, sg = idx & 15;
        size_t g = qbase + (size_t)r * (NH * HD) + sg * 8;
        cp16(base + r * LDVB + sg * 16,            qhi + g);
        cp16(base + 2 * FBUF + r * LDVB + sg * 16, qlo + g);
    }
    asm volatile("cp.async.commit_group;" ::: "memory");
    asm volatile("cp.async.wait_group 0;" ::: "memory");
    __syncthreads();

    uint32_t qa_h[8][4], qa_l[8][4];
    {
        const uint32_t qrow = base + (w * 16 + (lane & 15)) * LDVB + (lane >> 4) * 16;
#pragma unroll
        for (int ks = 0; ks < 8; ks++) {
            ldm_x4(qa_h[ks], qrow + ks * 32);
            ldm_x4(qa_l[ks], qrow + 2 * FBUF + ks * 32);
        }
    }
    __syncthreads();

    float o[16][4];
#pragma unroll
    for (int j = 0; j < 16; j++)
#pragma unroll
        for (int q = 0; q < 4; q++) o[j][q] = 0.f;
    float m0 = -CUDART_INF_F, m1 = -CUDART_INF_F, l0 = 0.f, l1 = 0.f;

    const int n = 2 * (qb + 1);
    load_kv(base, tid, khi, klo, vhi, vlo, kvh);

    const uint32_t koff = ((lane & 7) + ((lane >> 4) << 3)) * LDVB + ((lane >> 3) & 1) * 16;
    const uint32_t voff = (lane & 15) * LDVB + (lane >> 4) * 16;

    for (int t = 0; t < n; t++) {
        asm volatile("cp.async.wait_group 0;" ::: "memory");
        __syncthreads();
        if (t + 1 < n)
            load_kv(base + ((t + 1) & 1) * FSTG, tid, khi, klo, vhi, vlo,
                    kvh + (size_t)(t + 1) * 64 * (NKV * HD));

        const uint32_t sb = base + (t & 1) * FSTG;
        const uint32_t vbh = sb + 2 * FBUF + voff;

        float s[8][4];
#pragma unroll
        for (int f = 0; f < 8; f++)
#pragma unroll
            for (int q = 0; q < 4; q++) s[f][q] = 0.f;

#pragma unroll
        for (int ks = 0; ks < 8; ks++) {
#pragma unroll
            for (int g = 0; g < 4; g++) {
                uint32_t kbh[4], kbl[4];
                ldm_x4(kbh, sb + g * 16 * LDVB + ks * 32 + koff);
                ldm_x4(kbl, sb + FBUF + g * 16 * LDVB + ks * 32 + koff);
                mma16816(s[2 * g],     qa_h[ks], kbh[0], kbh[1]);
                mma16816(s[2 * g + 1], qa_h[ks], kbh[2], kbh[3]);
                mma16816(s[2 * g],     qa_h[ks], kbl[0], kbl[1]);
                mma16816(s[2 * g + 1], qa_h[ks], kbl[2], kbl[3]);
                mma16816(s[2 * g],     qa_l[ks], kbh[0], kbh[1]);
                mma16816(s[2 * g + 1], qa_l[ks], kbh[2], kbh[3]);
            }
        }

        if (t >= n - 2) {
            const int rA = q0 + w * 16 + (lane >> 2);
            const int cb = t * 64 + 2 * (lane & 3);
#pragma unroll
            for (int f = 0; f < 8; f++) {
                int c = cb + f * 8;
                if (c > rA)         s[f][0] = -1e30f;
                if (c + 1 > rA)     s[f][1] = -1e30f;
                if (c > rA + 8)     s[f][2] = -1e30f;
                if (c + 1 > rA + 8) s[f][3] = -1e30f;
            }
        }

        float mn0 = m0, mn1 = m1;
#pragma unroll
        for (int f = 0; f < 8; f++) {
            mn0 = fmaxf(mn0, fmaxf(s[f][0], s[f][1]));
            mn1 = fmaxf(mn1, fmaxf(s[f][2], s[f][3]));
        }
        mn0 = fmaxf(mn0, __shfl_xor_sync(0xffffffffu, mn0, 1));
        mn0 = fmaxf(mn0, __shfl_xor_sync(0xffffffffu, mn0, 2));
        mn1 = fmaxf(mn1, __shfl_xor_sync(0xffffffffu, mn1, 1));
        mn1 = fmaxf(mn1, __shfl_xor_sync(0xffffffffu, mn1, 2));
        const float cr0 = ex2(m0 - mn0), cr1 = ex2(m1 - mn1);
        m0 = mn0; m1 = mn1;
        l0 *= cr0; l1 *= cr1;
#pragma unroll
        for (int j = 0; j < 16; j++) {
            o[j][0] *= cr0; o[j][1] *= cr0;
            o[j][2] *= cr1; o[j][3] *= cr1;
        }

        float rs0 = 0.f, rs1 = 0.f;
        uint32_t ph01[8], ph23[8], pl01[8], pl23[8];
#pragma unroll
        for (int f = 0; f < 8; f++) {
            float p0 = ex2(s[f][0] - m0);
            float p1 = ex2(s[f][1] - m0);
            float p2 = ex2(s[f][2] - m1);
            float p3 = ex2(s[f][3] - m1);
            rs0 += p0 + p1;
            rs1 += p2 + p3;
            tsplit2(p0, p1, ph01[f], pl01[f]);
            tsplit2(p2, p3, ph23[f], pl23[f]);
        }
        l0 += rs0;
        l1 += rs1;

#pragma unroll
        for (int kc = 0; kc < 4; kc++) {
            uint32_t ah[4] = {ph01[2 * kc], ph23[2 * kc],
                              ph01[2 * kc + 1], ph23[2 * kc + 1]};
            uint32_t al[4] = {pl01[2 * kc], pl23[2 * kc],
                              pl01[2 * kc + 1], pl23[2 * kc + 1]};
#pragma unroll
            for (int g = 0; g < 8; g++) {
                uint32_t vh4[4], vl4[4];
                ldm_x4t(vh4, vbh + kc * 16 * LDVB + g * 32);
                ldm_x4t(vl4, vbh + FBUF + kc * 16 * LDVB + g * 32);
                mma16816(o[2 * g],     ah, vh4[0], vh4[1]);
                mma16816(o[2 * g + 1], ah, vh4[2], vh4[3]);
                mma16816(o[2 * g],     ah, vl4[0], vl4[1]);
                mma16816(o[2 * g + 1], ah, vl4[2], vl4[3]);
                mma16816(o[2 * g],     al, vh4[0], vh4[1]);
                mma16816(o[2 * g + 1], al, vh4[2], vh4[3]);
            }
        }
    }

    l0 += __shfl_xor_sync(0xffffffffu, l0, 1);
    l0 += __shfl_xor_sync(0xffffffffu, l0, 2);
    l1 += __shfl_xor_sync(0xffffffffu, l1, 1);
    l1 += __shfl_xor_sync(0xffffffffu, l1, 2);

    const float il0 = 1.f / l0, il1 = 1.f / l1;
    const int rA = q0 + w * 16 + (lane >> 2);
    const size_t oA = ((size_t)b * SEQ + rA) * (NH * HD) + (size_t)h * HD + 2 * (lane & 3);
    const size_t oB = oA + (size_t)8 * (NH * HD);
#pragma unroll
    for (int j = 0; j < 16; j++) {
        uint32_t h01, lo01, h23, lo23;
        split2(o[j][0] * il0, o[j][1] * il0, h01, lo01);
        split2(o[j][2] * il1, o[j][3] * il1, h23, lo23);
        *(uint32_t*)&ohi[oA + j * 8] = h01;
        *(uint32_t*)&olo[oA + j * 8] = lo01;
        *(uint32_t*)&ohi[oB + j * 8] = h23;
        *(uint32_t*)&olo[oB + j * 8] = lo23;
    }
}

// ---------------------------------------------------------------------------
// Launcher
// ---------------------------------------------------------------------------
extern "C" void kernel_launch(void* const* d_in, const int* in_sizes, int n_in,
                              void* d_out, int out_size)
{
    const float* data = (const float*)d_in[0];
    const float* Wq   = (const float*)d_in[1];
    const float* Wk   = (const float*)d_in[2];
    const float* Wv   = (const float*)d_in[3];
    const float* Wo   = (const float*)d_in[4];
    const float* cosT = (const float*)d_in[5];
    const float* sinT = (const float*)d_in[6];
    float* out = (float*)d_out;
    (void)in_sizes; (void)n_in; (void)out_size;

    __nv_bfloat16 *dh, *dl, *wqh, *wql, *wkh, *wkl, *wvh, *wvl, *woh, *wol, *ah, *al;
    __nv_bfloat16 *qsh, *qsl, *ksh, *ksl, *vsh, *vsl;
    cudaGetSymbolAddress((void**)&dh,  g_data_hi);
    cudaGetSymbolAddress((void**)&dl,  g_data_lo);
    cudaGetSymbolAddress((void**)&wqh, g_wq_hi);
    cudaGetSymbolAddress((void**)&wql, g_wq_lo);
    cudaGetSymbolAddress((void**)&wkh, g_wk_hi);
    cudaGetSymbolAddress((void**)&wkl, g_wk_lo);
    cudaGetSymbolAddress((void**)&wvh, g_wv_hi);
    cudaGetSymbolAddress((void**)&wvl, g_wv_lo);
    cudaGetSymbolAddress((void**)&woh, g_wo_hi);
    cudaGetSymbolAddress((void**)&wol, g_wo_lo);
    cudaGetSymbolAddress((void**)&ah,  g_attn_hi);
    cudaGetSymbolAddress((void**)&al,  g_attn_lo);
    cudaGetSymbolAddress((void**)&qsh, g_qs_hi);
    cudaGetSymbolAddress((void**)&qsl, g_qs_lo);
    cudaGetSymbolAddress((void**)&ksh, g_ks_hi);
    cudaGetSymbolAddress((void**)&ksl, g_ks_lo);
    cudaGetSymbolAddress((void**)&vsh, g_vs_hi);
    cudaGetSymbolAddress((void**)&vsl, g_vs_lo);

    cudaFuncSetAttribute(gemm_qkv,
                         cudaFuncAttributeMaxDynamicSharedMemorySize, GEMM_SMEM);
    cudaFuncSetAttribute(gemm_mm,
                         cudaFuncAttributeMaxDynamicSharedMemorySize, GEMM_SMEM);
    cudaFuncSetAttribute(flash_mma,
                         cudaFuncAttributeMaxDynamicSharedMemorySize, FLASH2_SMEM);

    // 1: weight splits
    split_w<<<(SPLIT_W_TOTAL + 255) / 256, 256>>>(Wq, Wk, Wv, Wo,
                                                  wqh, wql, wkh, wkl, wvh, wvl, woh, wol);
    // 2: data split
    split_d<<<(SPLIT_N_DATA + 255) / 256, 256>>>(data, dh, dl);

    // 3: fused QKV projection + RoPE + split (48 col tiles x 16 row tiles of 256)
    gemm_qkv<<<dim3(48, TOKENS / 256), 256, GEMM_SMEM>>>(
        dh, dl, wqh, wql, wkh, wkl, wvh, wvl,
        qsh, qsl, ksh, ksl, vsh, vsl, cosT, sinT);

    // 4: flash attention (profiled by ncu as the 4th launch)
    flash_mma<<<dim3(SEQ / 128, BATCH * NH), 256, FLASH2_SMEM>>>(
        qsh, qsl, ksh, ksl, vsh, vsl, ah, al);

    // 5: output projection (32 col tiles x 16 row tiles of 256)
    gemm_mm<<<dim3(DIM / 128, TOKENS / 256), 256, GEMM_SMEM>>>(ah, al, woh, wol, out, DIM);
}

// round 17
// speedup vs baseline: 1.1125x; 1.1125x over previous
#include <cuda_runtime.h>
#include <cuda_bf16.h>
#include <math_constants.h>
#include <cstdint>

// Problem constants
#define BATCH 2
#define SEQ 2048
#define DIM 4096
#define NH 32
#define NKV 8
#define HD 128
#define TOKENS (BATCH * SEQ)   // 4096

// ---------------------------------------------------------------------------
// Scratch (device globals; no runtime allocation allowed)
// ---------------------------------------------------------------------------
__device__ __nv_bfloat16 g_data_hi[(size_t)TOKENS * DIM];
__device__ __nv_bfloat16 g_data_lo[(size_t)TOKENS * DIM];
__device__ __nv_bfloat16 g_wq_hi[(size_t)(NH * HD) * DIM];
__device__ __nv_bfloat16 g_wq_lo[(size_t)(NH * HD) * DIM];
__device__ __nv_bfloat16 g_wk_hi[(size_t)(NKV * HD) * DIM];
__device__ __nv_bfloat16 g_wk_lo[(size_t)(NKV * HD) * DIM];
__device__ __nv_bfloat16 g_wv_hi[(size_t)(NKV * HD) * DIM];
__device__ __nv_bfloat16 g_wv_lo[(size_t)(NKV * HD) * DIM];
__device__ __nv_bfloat16 g_wo_hi[(size_t)DIM * (NH * HD)];
__device__ __nv_bfloat16 g_wo_lo[(size_t)DIM * (NH * HD)];
__device__ __nv_bfloat16 g_attn_hi[(size_t)TOKENS * (NH * HD)];
__device__ __nv_bfloat16 g_attn_lo[(size_t)TOKENS * (NH * HD)];

// Post-RoPE split Q/K and split V (bf16 hi/lo) — written by gemm_qkv epilogue
__device__ __nv_bfloat16 g_qs_hi[(size_t)TOKENS * (NH * HD)];
__device__ __nv_bfloat16 g_qs_lo[(size_t)TOKENS * (NH * HD)];
__device__ __nv_bfloat16 g_ks_hi[(size_t)TOKENS * (NKV * HD)];
__device__ __nv_bfloat16 g_ks_lo[(size_t)TOKENS * (NKV * HD)];
__device__ __nv_bfloat16 g_vs_hi[(size_t)TOKENS * (NKV * HD)];
__device__ __nv_bfloat16 g_vs_lo[(size_t)TOKENS * (NKV * HD)];

// ---------------------------------------------------------------------------
// PTX helpers (compute_103-legal: ldmatrix / mma.sync / cp.async only)
// ---------------------------------------------------------------------------
__device__ __forceinline__ uint32_t smem_u32(const void* p) {
    uint32_t a;
    asm("{ .reg .u64 t; cvta.to.shared.u64 t, %1; cvt.u32.u64 %0, t; }"
        : "=r"(a) : "l"(p));
    return a;
}
__device__ __forceinline__ void cp16(uint32_t saddr, const void* g) {
    asm volatile("cp.async.cg.shared.global [%0], [%1], 16;" :: "r"(saddr), "l"(g));
}
__device__ __forceinline__ void ldm_x4(uint32_t* r, uint32_t addr) {
    asm volatile("ldmatrix.sync.aligned.m8n8.x4.shared.b16 {%0,%1,%2,%3}, [%4];"
                 : "=r"(r[0]), "=r"(r[1]), "=r"(r[2]), "=r"(r[3]) : "r"(addr));
}
__device__ __forceinline__ void ldm_x4t(uint32_t* r, uint32_t addr) {
    asm volatile("ldmatrix.sync.aligned.m8n8.x4.trans.shared.b16 {%0,%1,%2,%3}, [%4];"
                 : "=r"(r[0]), "=r"(r[1]), "=r"(r[2]), "=r"(r[3]) : "r"(addr));
}
__device__ __forceinline__ void mma16816(float* d, const uint32_t* a,
                                         uint32_t b0, uint32_t b1) {
    asm volatile(
        "mma.sync.aligned.m16n8k16.row.col.f32.bf16.bf16.f32 "
        "{%0,%1,%2,%3}, {%4,%5,%6,%7}, {%8,%9}, {%0,%1,%2,%3};"
        : "+f"(d[0]), "+f"(d[1]), "+f"(d[2]), "+f"(d[3])
        : "r"(a[0]), "r"(a[1]), "r"(a[2]), "r"(a[3]), "r"(b0), "r"(b1));
}
__device__ __forceinline__ float ex2(float x) {
    float r;
    asm("ex2.approx.f32 %0, %1;" : "=f"(r) : "f"(x));
    return r;
}
// RN-based split
__device__ __forceinline__ void split2(float a, float b, uint32_t& hi, uint32_t& lo) {
    __nv_bfloat16 ha = __float2bfloat16(a), hb = __float2bfloat16(b);
    __nv_bfloat162 H(ha, hb);
    __nv_bfloat162 L(__float2bfloat16(a - __bfloat162float(ha)),
                     __float2bfloat16(b - __bfloat162float(hb)));
    hi = *reinterpret_cast<uint32_t*>(&H);
    lo = *reinterpret_cast<uint32_t*>(&L);
}
// Truncation-based split (P in flash; hi+lo together keep full precision)
__device__ __forceinline__ void tsplit2(float a, float b, uint32_t& hi, uint32_t& lo) {
    uint32_t ua = __float_as_uint(a), ub = __float_as_uint(b);
    asm("prmt.b32 %0, %1, %2, 0x7632;" : "=r"(hi) : "r"(ua), "r"(ub));
    float ra = a - __uint_as_float(ua & 0xFFFF0000u);
    float rb = b - __uint_as_float(ub & 0xFFFF0000u);
    asm("cvt.rn.bf16x2.f32 %0, %1, %2;" : "=r"(lo) : "f"(rb), "f"(ra));
}

// ---------------------------------------------------------------------------
// HMMA GEMM core, 3 split terms per chunk, ONE barrier per chunk (round-14).
// Loop: wait(load c) | bar | issue load(c+1) | MMAs(c).
// Tile 128x128, BK=32, 2-stage cp.async (40KB/stage), 8 warps 4m x 2n.
// EPI: 0 = fp32 C, 1 = rope+scale+split -> Ohi/Olo, 2 = split-only -> Ohi/Olo
// ---------------------------------------------------------------------------
#define GK 4096
#define BKC 32
#define NCHUNK2 (GK / BKC)           // 128
#define LDA 40
#define ABUF_B (128 * LDA * 2)       // 10240 B per array
#define OFF_AL ABUF_B
#define OFF_BH (2 * ABUF_B)
#define OFF_BL (3 * ABUF_B)
#define STAGE2_BYTES (4 * ABUF_B)    // 40960
#define GEMM_SMEM (2 * STAGE2_BYTES) // 81920

__device__ __forceinline__ void load_chunk_mm(
    int kc, uint32_t sbase, int tid, int m0, int n0,
    const __nv_bfloat16* __restrict__ Ahi, const __nv_bfloat16* __restrict__ Alo,
    const __nv_bfloat16* __restrict__ Bhi, const __nv_bfloat16* __restrict__ Blo)
{
    const size_t ke = (size_t)kc * BKC;
    const int r0 = tid >> 2;
    const int seg = (tid & 3) * 8;
#pragma unroll
    for (int it = 0; it < 2; it++) {
        int r = r0 + it * 64;
        uint32_t srow = sbase + (uint32_t)(r * LDA + seg) * 2;
        size_t ga = (size_t)(m0 + r) * GK + ke + seg;
        size_t gb = (size_t)(n0 + r) * GK + ke + seg;
        cp16(srow,          Ahi + ga);
        cp16(srow + OFF_AL, Alo + ga);
        cp16(srow + OFF_BH, Bhi + gb);
        cp16(srow + OFF_BL, Blo + gb);
    }
    asm volatile("cp.async.commit_group;" ::: "memory");
}

template <int EPI>
__device__ __forceinline__ void gemm_core(
    const __nv_bfloat16* __restrict__ Ahi, const __nv_bfloat16* __restrict__ Alo,
    const __nv_bfloat16* __restrict__ Bhi, const __nv_bfloat16* __restrict__ Blo,
    float* __restrict__ C,
    __nv_bfloat16* __restrict__ Ohi, __nv_bfloat16* __restrict__ Olo,
    const float* __restrict__ cosT, const float* __restrict__ sinT, float scale,
    int Ng, int m0, int n0, char* dsm)
{
    const uint32_t base = smem_u32(dsm);
    const int tid = threadIdx.x;
    const int lane = tid & 31;
    const int w = tid >> 5;
    const int wm = (w >> 1) * 32;
    const int wn = (w & 1) * 64;

    float acc[2][8][4];
#pragma unroll
    for (int f = 0; f < 2; f++)
#pragma unroll
        for (int j = 0; j < 8; j++)
#pragma unroll
            for (int q = 0; q < 4; q++) acc[f][j][q] = 0.f;

    const uint32_t a_off = (uint32_t)(((lane & 15)) * LDA + ((lane >> 4) * 8)) * 2;
    const uint32_t b_off = (uint32_t)(((lane & 7) + ((lane >> 4) << 3)) * LDA
                                      + (((lane >> 3) & 1) * 8)) * 2;

    load_chunk_mm(0, base, tid, m0, n0, Ahi, Alo, Bhi, Blo);

    for (int c = 0; c < NCHUNK2; c++) {
        // load(c) is the only outstanding group here (load(c+1) not yet issued)
        asm volatile("cp.async.wait_group 0;" ::: "memory");
        __syncthreads();   // all warps: past MMAs(c-1), and see load(c)

        if (c + 1 < NCHUNK2)
            load_chunk_mm(c + 1, base + ((c + 1) & 1) * STAGE2_BYTES,
                          tid, m0, n0, Ahi, Alo, Bhi, Blo);

        const uint32_t sb = base + (c & 1) * STAGE2_BYTES;
        const uint32_t abh = sb + (uint32_t)(wm * LDA * 2) + a_off;
        const uint32_t bbh = sb + OFF_BH + (uint32_t)(wn * LDA * 2) + b_off;

#pragma unroll
        for (int ks = 0; ks < 2; ks++) {
            uint32_t a0h[4], a1h[4], a0l[4], a1l[4];
            ldm_x4(a0h, abh + ks * 32);
            ldm_x4(a1h, abh + ks * 32 + 16 * LDA * 2);
            ldm_x4(a0l, abh + OFF_AL + ks * 32);
            ldm_x4(a1l, abh + OFF_AL + ks * 32 + 16 * LDA * 2);
#pragma unroll
            for (int g = 0; g < 4; g++) {
                uint32_t bh[4];
                ldm_x4(bh, bbh + ks * 32 + g * (16 * LDA * 2));
                mma16816(acc[0][2 * g],     a0h, bh[0], bh[1]);
                mma16816(acc[0][2 * g + 1], a0h, bh[2], bh[3]);
                mma16816(acc[1][2 * g],     a1h, bh[0], bh[1]);
                mma16816(acc[1][2 * g + 1], a1h, bh[2], bh[3]);
                mma16816(acc[0][2 * g],     a0l, bh[0], bh[1]);
                mma16816(acc[0][2 * g + 1], a0l, bh[2], bh[3]);
                mma16816(acc[1][2 * g],     a1l, bh[0], bh[1]);
                mma16816(acc[1][2 * g + 1], a1l, bh[2], bh[3]);
                uint32_t bl[4];
                ldm_x4(bl, bbh + (OFF_BL - OFF_BH) + ks * 32 + g * (16 * LDA * 2));
                mma16816(acc[0][2 * g],     a0h, bl[0], bl[1]);
                mma16816(acc[0][2 * g + 1], a0h, bl[2], bl[3]);
                mma16816(acc[1][2 * g],     a1h, bl[0], bl[1]);
                mma16816(acc[1][2 * g + 1], a1h, bl[2], bl[3]);
            }
        }
    }

    const int gr = lane >> 2;
    const int gc = (lane & 3) * 2;

    if (EPI == 0) {
        // Pack rows through registers and emit float4 stores (col-pairs j,j+1)
#pragma unroll
        for (int f = 0; f < 2; f++) {
            const int row = m0 + wm + f * 16 + gr;
#pragma unroll
            for (int j = 0; j < 8; j += 2) {
                const int col = n0 + wn + j * 8 + gc;
                // two float2 groups 8 cols apart cannot merge; store float2 pairs
                *(float2*)&C[(size_t)row * Ng + col] =
                    make_float2(acc[f][j][0], acc[f][j][1]);
                *(float2*)&C[(size_t)row * Ng + col + 8] =
                    make_float2(acc[f][j + 1][0], acc[f][j + 1][1]);
                *(float2*)&C[(size_t)(row + 8) * Ng + col] =
                    make_float2(acc[f][j][2], acc[f][j][3]);
                *(float2*)&C[(size_t)(row + 8) * Ng + col + 8] =
                    make_float2(acc[f][j + 1][2], acc[f][j + 1][3]);
            }
        }
    } else if (EPI == 2) {
#pragma unroll
        for (int f = 0; f < 2; f++) {
            const int row = m0 + wm + f * 16 + gr;
#pragma unroll
            for (int j = 0; j < 8; j++) {
                const int col = n0 + wn + j * 8 + gc;
                uint32_t h, l;
                split2(acc[f][j][0], acc[f][j][1], h, l);
                *(uint32_t*)&Ohi[(size_t)row * Ng + col] = h;
                *(uint32_t*)&Olo[(size_t)row * Ng + col] = l;
                split2(acc[f][j][2], acc[f][j][3], h, l);
                *(uint32_t*)&Ohi[(size_t)(row + 8) * Ng + col] = h;
                *(uint32_t*)&Olo[(size_t)(row + 8) * Ng + col] = l;
            }
        }
    } else {
        __syncthreads();   // all MMAs done before smem reuse for exchange
        float* xs = (float*)dsm;   // [128][66]
        if (w & 1) {
#pragma unroll
            for (int f = 0; f < 2; f++) {
                const int rl = wm + f * 16 + gr;
#pragma unroll
                for (int j = 0; j < 8; j++) {
                    const int dd = j * 8 + gc;
                    xs[rl * 66 + dd]       = acc[f][j][0];
                    xs[rl * 66 + dd + 1]   = acc[f][j][1];
                    xs[(rl + 8) * 66 + dd]     = acc[f][j][2];
                    xs[(rl + 8) * 66 + dd + 1] = acc[f][j][3];
                }
            }
        }
        __syncthreads();
        if (!(w & 1)) {
#pragma unroll
            for (int f = 0; f < 2; f++) {
#pragma unroll
                for (int fr = 0; fr < 2; fr++) {
                    const int rl = wm + f * 16 + gr + fr * 8;
                    const int row = m0 + rl;
                    const int s = row & (SEQ - 1);
#pragma unroll
                    for (int j = 0; j < 8; j++) {
                        const int d = j * 8 + gc;
                        float x1a = acc[f][j][fr * 2];
                        float x1b = acc[f][j][fr * 2 + 1];
                        float x2a = xs[rl * 66 + d];
                        float x2b = xs[rl * 66 + d + 1];
                        float c0 = cosT[s * HD + d],     s0 = sinT[s * HD + d];
                        float c1 = cosT[s * HD + d + 1], s1 = sinT[s * HD + d + 1];
                        float y1a = (x1a * c0 - x2a * s0) * scale;
                        float y2a = (x2a * c0 + x1a * s0) * scale;
                        float y1b = (x1b * c1 - x2b * s1) * scale;
                        float y2b = (x2b * c1 + x1b * s1) * scale;
                        uint32_t h, l;
                        split2(y1a, y1b, h, l);
                        *(uint32_t*)&Ohi[(size_t)row * Ng + n0 + d] = h;
                        *(uint32_t*)&Olo[(size_t)row * Ng + n0 + d] = l;
                        split2(y2a, y2b, h, l);
                        *(uint32_t*)&Ohi[(size_t)row * Ng + n0 + 64 + d] = h;
                        *(uint32_t*)&Olo[(size_t)row * Ng + n0 + 64 + d] = l;
                    }
                }
            }
        }
    }
}

#define QSCALE (0.08838834764831845f * 1.4426950408889634f)

// Fused QKV projection + RoPE + split: bx 0..31 Q, 32..39 K, 40..47 V
__global__ __launch_bounds__(256, 2) void gemm_qkv(
    const __nv_bfloat16* __restrict__ dh, const __nv_bfloat16* __restrict__ dl,
    const __nv_bfloat16* __restrict__ wqh, const __nv_bfloat16* __restrict__ wql,
    const __nv_bfloat16* __restrict__ wkh, const __nv_bfloat16* __restrict__ wkl,
    const __nv_bfloat16* __restrict__ wvh, const __nv_bfloat16* __restrict__ wvl,
    __nv_bfloat16* __restrict__ qsh, __nv_bfloat16* __restrict__ qsl,
    __nv_bfloat16* __restrict__ ksh, __nv_bfloat16* __restrict__ ksl,
    __nv_bfloat16* __restrict__ vsh, __nv_bfloat16* __restrict__ vsl,
    const float* __restrict__ cosT, const float* __restrict__ sinT)
{
    extern __shared__ char dsm[];
    const int bx = blockIdx.x;
    const int m0 = blockIdx.y * 128;
    if (bx < 32) {
        gemm_core<1>(dh, dl, wqh, wql, nullptr, qsh, qsl, cosT, sinT, QSCALE,
                     NH * HD, m0, bx * 128, dsm);
    } else if (bx < 40) {
        gemm_core<1>(dh, dl, wkh, wkl, nullptr, ksh, ksl, cosT, sinT, 1.0f,
                     NKV * HD, m0, (bx - 32) * 128, dsm);
    } else {
        gemm_core<2>(dh, dl, wvh, wvl, nullptr, vsh, vsl, nullptr, nullptr, 1.0f,
                     NKV * HD, m0, (bx - 40) * 128, dsm);
    }
}

// O projection (plain fp32 epilogue)
__global__ __launch_bounds__(256, 2) void gemm_mm(
    const __nv_bfloat16* __restrict__ Ahi, const __nv_bfloat16* __restrict__ Alo,
    const __nv_bfloat16* __restrict__ Bhi, const __nv_bfloat16* __restrict__ Blo,
    float* __restrict__ C, int Ng)
{
    extern __shared__ char dsm[];
    gemm_core<0>(Ahi, Alo, Bhi, Blo, C, nullptr, nullptr, nullptr, nullptr, 1.0f,
                 Ng, blockIdx.y * 128, blockIdx.x * 128, dsm);
}

// ---------------------------------------------------------------------------
// One fused split kernel for all 5 fp32 inputs (sizes in float4 units)
// ---------------------------------------------------------------------------
#define SPLIT_N_DATA  4194304
#define SPLIT_N_WQ    4194304
#define SPLIT_N_WK    1048576
#define SPLIT_N_WV    1048576
#define SPLIT_N_WO    4194304
#define SPLIT_TOTAL   (SPLIT_N_DATA + SPLIT_N_WQ + SPLIT_N_WK + SPLIT_N_WV + SPLIT_N_WO)

__global__ void split_all(
    const float* __restrict__ data, const float* __restrict__ Wq,
    const float* __restrict__ Wk, const float* __restrict__ Wv,
    const float* __restrict__ Wo,
    __nv_bfloat16* __restrict__ dh, __nv_bfloat16* __restrict__ dl,
    __nv_bfloat16* __restrict__ qh, __nv_bfloat16* __restrict__ ql,
    __nv_bfloat16* __restrict__ kh, __nv_bfloat16* __restrict__ kl,
    __nv_bfloat16* __restrict__ vh, __nv_bfloat16* __restrict__ vl,
    __nv_bfloat16* __restrict__ oh, __nv_bfloat16* __restrict__ ol)
{
    int i = blockIdx.x * 256 + threadIdx.x;
    if (i >= SPLIT_TOTAL) return;
    const float* src; __nv_bfloat16 *hi, *lo; int off;
    if (i < SPLIT_N_DATA) { src = data; hi = dh; lo = dl; off = 0; }
    else if (i < SPLIT_N_DATA + SPLIT_N_WQ)
        { src = Wq; hi = qh; lo = ql; off = SPLIT_N_DATA; }
    else if (i < SPLIT_N_DATA + SPLIT_N_WQ + SPLIT_N_WK)
        { src = Wk; hi = kh; lo = kl; off = SPLIT_N_DATA + SPLIT_N_WQ; }
    else if (i < SPLIT_N_DATA + SPLIT_N_WQ + SPLIT_N_WK + SPLIT_N_WV)
        { src = Wv; hi = vh; lo = vl; off = SPLIT_N_DATA + SPLIT_N_WQ + SPLIT_N_WK; }
    else
        { src = Wo; hi = oh; lo = ol; off = SPLIT_N_DATA + SPLIT_N_WQ + SPLIT_N_WK + SPLIT_N_WV; }
    int j = i - off;
    float4 val = ((const float4*)src)[j];
    uint32_t h01, l01, h23, l23;
    split2(val.x, val.y, h01, l01);
    split2(val.z, val.w, h23, l23);
    ((uint32_t*)hi)[j * 2]     = h01;
    ((uint32_t*)hi)[j * 2 + 1] = h23;
    ((uint32_t*)lo)[j * 2]     = l01;
    ((uint32_t*)lo)[j * 2 + 1] = l23;
}

// ---------------------------------------------------------------------------
// Flash attention on HMMA (round-10/14 best version, unchanged).
// BQ=128, BKV=64, 8 warps x 16 q-rows, 2-stage KV double buffer.
// ---------------------------------------------------------------------------
#define LDV 136
#define LDVB (LDV * 2)
#define FBUF (64 * LDVB)
#define FSTG (4 * FBUF)
#define FLASH2_SMEM (2 * FSTG)

__device__ __forceinline__ void load_kv(uint32_t sb, int tid,
    const __nv_bfloat16* __restrict__ khi, const __nv_bfloat16* __restrict__ klo,
    const __nv_bfloat16* __restrict__ vhi, const __nv_bfloat16* __restrict__ vlo,
    size_t kvbase)
{
#pragma unroll
    for (int i = 0; i < 4; i++) {
        int idx = tid + i * 256;
        int r = idx >> 4, sg = idx & 15;
        size_t g = kvbase + (size_t)r * (NKV * HD) + sg * 8;
        uint32_t s = sb + r * LDVB + sg * 16;
        cp16(s,            khi + g);
        cp16(s + FBUF,     klo + g);
        cp16(s + 2 * FBUF, vhi + g);
        cp16(s + 3 * FBUF, vlo + g);
    }
    asm volatile("cp.async.commit_group;" ::: "memory");
}

__global__ __launch_bounds__(256) void flash_mma(
    const __nv_bfloat16* __restrict__ qhi, const __nv_bfloat16* __restrict__ qlo,
    const __nv_bfloat16* __restrict__ khi, const __nv_bfloat16* __restrict__ klo,
    const __nv_bfloat16* __restrict__ vhi, const __nv_bfloat16* __restrict__ vlo,
    __nv_bfloat16* __restrict__ ohi, __nv_bfloat16* __restrict__ olo)
{
    extern __shared__ char dsm[];
    const uint32_t base = smem_u32(dsm);
    const int tid = threadIdx.x;
    const int lane = tid & 31;
    const int w = tid >> 5;
    const int qb = gridDim.x - 1 - blockIdx.x;   // heavy tiles first
    const int bh = blockIdx.y;
    const int b = bh / NH, h = bh % NH;
    const int kh = h / (NH / NKV);
    const int q0 = qb * 128;

    const size_t qbase = ((size_t)b * SEQ + q0) * (NH * HD) + (size_t)h * HD;
    const size_t kvh   = ((size_t)b * SEQ) * (NKV * HD) + (size_t)kh * HD;

#pragma unroll
    for (int i = 0; i < 8; i++) {
        int idx = tid + i * 256;
        int r = idx >> 4, sg = idx & 15;
        size_t g = qbase + (size_t)r * (NH * HD) + sg * 8;
        cp16(base + r * LDVB + sg * 16,            qhi + g);
        cp16(base + 2 * FBUF + r * LDVB + sg * 16, qlo + g);
    }
    asm volatile("cp.async.commit_group;" ::: "memory");
    asm volatile("cp.async.wait_group 0;" ::: "memory");
    __syncthreads();

    uint32_t qa_h[8][4], qa_l[8][4];
    {
        const uint32_t qrow = base + (w * 16 + (lane & 15)) * LDVB + (lane >> 4) * 16;
#pragma unroll
        for (int ks = 0; ks < 8; ks++) {
            ldm_x4(qa_h[ks], qrow + ks * 32);
            ldm_x4(qa_l[ks], qrow + 2 * FBUF + ks * 32);
        }
    }
    __syncthreads();

    float o[16][4];
#pragma unroll
    for (int j = 0; j < 16; j++)
#pragma unroll
        for (int q = 0; q < 4; q++) o[j][q] = 0.f;
    float m0 = -CUDART_INF_F, m1 = -CUDART_INF_F, l0 = 0.f, l1 = 0.f;

    const int n = 2 * (qb + 1);
    load_kv(base, tid, khi, klo, vhi, vlo, kvh);

    const uint32_t koff = ((lane & 7) + ((lane >> 4) << 3)) * LDVB + ((lane >> 3) & 1) * 16;
    const uint32_t voff = (lane & 15) * LDVB + (lane >> 4) * 16;

    for (int t = 0; t < n; t++) {
        asm volatile("cp.async.wait_group 0;" ::: "memory");
        __syncthreads();
        if (t + 1 < n)
            load_kv(base + ((t + 1) & 1) * FSTG, tid, khi, klo, vhi, vlo,
                    kvh + (size_t)(t + 1) * 64 * (NKV * HD));

        const uint32_t sb = base + (t & 1) * FSTG;
        const uint32_t vbh = sb + 2 * FBUF + voff;

        float s[8][4];
#pragma unroll
        for (int f = 0; f < 8; f++)
#pragma unroll
            for (int q = 0; q < 4; q++) s[f][q] = 0.f;

#pragma unroll
        for (int ks = 0; ks < 8; ks++) {
#pragma unroll
            for (int g = 0; g < 4; g++) {
                uint32_t kbh[4], kbl[4];
                ldm_x4(kbh, sb + g * 16 * LDVB + ks * 32 + koff);
                ldm_x4(kbl, sb + FBUF + g * 16 * LDVB + ks * 32 + koff);
                mma16816(s[2 * g],     qa_h[ks], kbh[0], kbh[1]);
                mma16816(s[2 * g + 1], qa_h[ks], kbh[2], kbh[3]);
                mma16816(s[2 * g],     qa_h[ks], kbl[0], kbl[1]);
                mma16816(s[2 * g + 1], qa_h[ks], kbl[2], kbl[3]);
                mma16816(s[2 * g],     qa_l[ks], kbh[0], kbh[1]);
                mma16816(s[2 * g + 1], qa_l[ks], kbh[2], kbh[3]);
            }
        }

        if (t >= n - 2) {
            const int rA = q0 + w * 16 + (lane >> 2);
            const int cb = t * 64 + 2 * (lane & 3);
#pragma unroll
            for (int f = 0; f < 8; f++) {
                int c = cb + f * 8;
                if (c > rA)         s[f][0] = -1e30f;
                if (c + 1 > rA)     s[f][1] = -1e30f;
                if (c > rA + 8)     s[f][2] = -1e30f;
                if (c + 1 > rA + 8) s[f][3] = -1e30f;
            }
        }

        float mn0 = m0, mn1 = m1;
#pragma unroll
        for (int f = 0; f < 8; f++) {
            mn0 = fmaxf(mn0, fmaxf(s[f][0], s[f][1]));
            mn1 = fmaxf(mn1, fmaxf(s[f][2], s[f][3]));
        }
        mn0 = fmaxf(mn0, __shfl_xor_sync(0xffffffffu, mn0, 1));
        mn0 = fmaxf(mn0, __shfl_xor_sync(0xffffffffu, mn0, 2));
        mn1 = fmaxf(mn1, __shfl_xor_sync(0xffffffffu, mn1, 1));
        mn1 = fmaxf(mn1, __shfl_xor_sync(0xffffffffu, mn1, 2));
        const float cr0 = ex2(m0 - mn0), cr1 = ex2(m1 - mn1);
        m0 = mn0; m1 = mn1;
        l0 *= cr0; l1 *= cr1;
#pragma unroll
        for (int j = 0; j < 16; j++) {
            o[j][0] *= cr0; o[j][1] *= cr0;
            o[j][2] *= cr1; o[j][3] *= cr1;
        }

        float rs0 = 0.f, rs1 = 0.f;
        uint32_t ph01[8], ph23[8], pl01[8], pl23[8];
#pragma unroll
        for (int f = 0; f < 8; f++) {
            float p0 = ex2(s[f][0] - m0);
            float p1 = ex2(s[f][1] - m0);
            float p2 = ex2(s[f][2] - m1);
            float p3 = ex2(s[f][3] - m1);
            rs0 += p0 + p1;
            rs1 += p2 + p3;
            tsplit2(p0, p1, ph01[f], pl01[f]);
            tsplit2(p2, p3, ph23[f], pl23[f]);
        }
        l0 += rs0;
        l1 += rs1;

#pragma unroll
        for (int kc = 0; kc < 4; kc++) {
            uint32_t ah[4] = {ph01[2 * kc], ph23[2 * kc],
                              ph01[2 * kc + 1], ph23[2 * kc + 1]};
            uint32_t al[4] = {pl01[2 * kc], pl23[2 * kc],
                              pl01[2 * kc + 1], pl23[2 * kc + 1]};
#pragma unroll
            for (int g = 0; g < 8; g++) {
                uint32_t vh4[4], vl4[4];
                ldm_x4t(vh4, vbh + kc * 16 * LDVB + g * 32);
                ldm_x4t(vl4, vbh + FBUF + kc * 16 * LDVB + g * 32);
                mma16816(o[2 * g],     ah, vh4[0], vh4[1]);
                mma16816(o[2 * g + 1], ah, vh4[2], vh4[3]);
                mma16816(o[2 * g],     ah, vl4[0], vl4[1]);
                mma16816(o[2 * g + 1], ah, vl4[2], vl4[3]);
                mma16816(o[2 * g],     al, vh4[0], vh4[1]);
                mma16816(o[2 * g + 1], al, vh4[2], vh4[3]);
            }
        }
    }

    l0 += __shfl_xor_sync(0xffffffffu, l0, 1);
    l0 += __shfl_xor_sync(0xffffffffu, l0, 2);
    l1 += __shfl_xor_sync(0xffffffffu, l1, 1);
    l1 += __shfl_xor_sync(0xffffffffu, l1, 2);

    const float il0 = 1.f / l0, il1 = 1.f / l1;
    const int rA = q0 + w * 16 + (lane >> 2);
    const size_t oA = ((size_t)b * SEQ + rA) * (NH * HD) + (size_t)h * HD + 2 * (lane & 3);
    const size_t oB = oA + (size_t)8 * (NH * HD);
#pragma unroll
    for (int j = 0; j < 16; j++) {
        uint32_t h01, lo01, h23, lo23;
        split2(o[j][0] * il0, o[j][1] * il0, h01, lo01);
        split2(o[j][2] * il1, o[j][3] * il1, h23, lo23);
        *(uint32_t*)&ohi[oA + j * 8] = h01;
        *(uint32_t*)&olo[oA + j * 8] = lo01;
        *(uint32_t*)&ohi[oB + j * 8] = h23;
        *(uint32_t*)&olo[oB + j * 8] = lo23;
    }
}

// ---------------------------------------------------------------------------
// Launcher
// ---------------------------------------------------------------------------
extern "C" void kernel_launch(void* const* d_in, const int* in_sizes, int n_in,
                              void* d_out, int out_size)
{
    const float* data = (const float*)d_in[0];
    const float* Wq   = (const float*)d_in[1];
    const float* Wk   = (const float*)d_in[2];
    const float* Wv   = (const float*)d_in[3];
    const float* Wo   = (const float*)d_in[4];
    const float* cosT = (const float*)d_in[5];
    const float* sinT = (const float*)d_in[6];
    float* out = (float*)d_out;
    (void)in_sizes; (void)n_in; (void)out_size;

    __nv_bfloat16 *dh, *dl, *wqh, *wql, *wkh, *wkl, *wvh, *wvl, *woh, *wol, *ah, *al;
    __nv_bfloat16 *qsh, *qsl, *ksh, *ksl, *vsh, *vsl;
    cudaGetSymbolAddress((void**)&dh,  g_data_hi);
    cudaGetSymbolAddress((void**)&dl,  g_data_lo);
    cudaGetSymbolAddress((void**)&wqh, g_wq_hi);
    cudaGetSymbolAddress((void**)&wql, g_wq_lo);
    cudaGetSymbolAddress((void**)&wkh, g_wk_hi);
    cudaGetSymbolAddress((void**)&wkl, g_wk_lo);
    cudaGetSymbolAddress((void**)&wvh, g_wv_hi);
    cudaGetSymbolAddress((void**)&wvl, g_wv_lo);
    cudaGetSymbolAddress((void**)&woh, g_wo_hi);
    cudaGetSymbolAddress((void**)&wol, g_wo_lo);
    cudaGetSymbolAddress((void**)&ah,  g_attn_hi);
    cudaGetSymbolAddress((void**)&al,  g_attn_lo);
    cudaGetSymbolAddress((void**)&qsh, g_qs_hi);
    cudaGetSymbolAddress((void**)&qsl, g_qs_lo);
    cudaGetSymbolAddress((void**)&ksh, g_ks_hi);
    cudaGetSymbolAddress((void**)&ksl, g_ks_lo);
    cudaGetSymbolAddress((void**)&vsh, g_vs_hi);
    cudaGetSymbolAddress((void**)&vsl, g_vs_lo);

    cudaFuncSetAttribute(gemm_qkv,
                         cudaFuncAttributeMaxDynamicSharedMemorySize, GEMM_SMEM);
    cudaFuncSetAttribute(gemm_mm,
                         cudaFuncAttributeMaxDynamicSharedMemorySize, GEMM_SMEM);
    cudaFuncSetAttribute(flash_mma,
                         cudaFuncAttributeMaxDynamicSharedMemorySize, FLASH2_SMEM);

    // 1: all input splits (one launch)
    split_all<<<(SPLIT_TOTAL + 255) / 256, 256>>>(data, Wq, Wk, Wv, Wo,
                                          dh, dl, wqh, wql, wkh, wkl, wvh, wvl, woh, wol);

    // 2: fused QKV projection + RoPE + split (48 column tiles)
    gemm_qkv<<<dim3(48, TOKENS / 128), 256, GEMM_SMEM>>>(
        dh, dl, wqh, wql, wkh, wkl, wvh, wvl,
        qsh, qsl, ksh, ksl, vsh, vsl, cosT, sinT);

    // 3: flash attention (writes bf16 hi/lo)
    flash_mma<<<dim3(SEQ / 128, BATCH * NH), 256, FLASH2_SMEM>>>(
        qsh, qsl, ksh, ksl, vsh, vsl, ah, al);

    // 4: output projection
    gemm_mm<<<dim3(DIM / 128, TOKENS / 128), 256, GEMM_SMEM>>>(ah, al, woh, wol, out, DIM);
}